// round 4
// baseline (speedup 1.0000x reference)
#include <cuda_runtime.h>

#define NN 50000
#define NE 1600000
#define NG 512
#define NL 3
#define D 128
#define EF 16
#define BN_EPS 1e-5f

// Scratch (device globals: allocation-free rule)
__device__ float g_h[NN * D];          // node features after each layer
__device__ float g_aggr[NN * D];       // scatter-add accumulator
__device__ float g_pool[NG * NL * D];  // per-graph pooled features (concat layout)

// ---------------------------------------------------------------------------
// Edge kernel: one warp per edge.
//   e   = edge_attr[e] @ el_W + el_b        (el_W held in registers: 16x4/lane)
//   m   = relu(h[src] + e)
//   aggr[dst] += m                          (fp32 atomics, L2-resident)
// ---------------------------------------------------------------------------
__global__ void __launch_bounds__(256) edge_kernel(
    const float* __restrict__ h,
    const float* __restrict__ edge_attr,
    const float* __restrict__ elW,   // [EF, D] for this layer
    const float* __restrict__ elb,   // [D]
    const int* __restrict__ ei)      // int32 (JAX x64 disabled downcasts int64)
{
    const int lane = threadIdx.x & 31;
    const int warp = threadIdx.x >> 5;
    const int gw = blockIdx.x * 8 + warp;
    const int nw = gridDim.x * 8;

    // Preload edge-linear weights for this lane's 4 dims (d = lane*4 + j)
    float wr[EF][4];
    float br[4];
#pragma unroll
    for (int j = 0; j < 4; j++) {
        br[j] = elb[lane * 4 + j];
#pragma unroll
        for (int f = 0; f < EF; f++)
            wr[f][j] = elW[f * D + lane * 4 + j];
    }

    for (int e = gw; e < NE; e += nw) {
        const int src = ei[e];
        const int dst = ei[NE + e];

        float av = (lane < EF) ? __ldg(edge_attr + (size_t)e * EF + lane) : 0.0f;

        float a0 = br[0], a1 = br[1], a2 = br[2], a3 = br[3];
#pragma unroll
        for (int f = 0; f < EF; f++) {
            const float a = __shfl_sync(0xffffffffu, av, f);
            a0 += a * wr[f][0];
            a1 += a * wr[f][1];
            a2 += a * wr[f][2];
            a3 += a * wr[f][3];
        }

        const float4 hv = *(const float4*)(h + (size_t)src * D + lane * 4);
        a0 = fmaxf(a0 + hv.x, 0.0f);
        a1 = fmaxf(a1 + hv.y, 0.0f);
        a2 = fmaxf(a2 + hv.z, 0.0f);
        a3 = fmaxf(a3 + hv.w, 0.0f);

        float* ag = g_aggr + (size_t)dst * D + lane * 4;
        atomicAdd(ag + 0, a0);
        atomicAdd(ag + 1, a1);
        atomicAdd(ag + 2, a2);
        atomicAdd(ag + 3, a3);
    }
}

// ---------------------------------------------------------------------------
// Node MLP kernel: persistent, one warp per node (grid-stride).
//   z = h + aggr
//   t = relu(bn(z @ W1 + b1))     (BN folded into W1/b1 at smem-load time)
//   hN = relu(t @ W2 + b2)
//   g_h[n] = hN;  pool[batch[n]] += hN
// ---------------------------------------------------------------------------
__global__ void __launch_bounds__(512) node_kernel(
    const float* __restrict__ h_in,
    const float* __restrict__ W1, const float* __restrict__ b1,
    const float* __restrict__ bng, const float* __restrict__ bnb,
    const float* __restrict__ bnm, const float* __restrict__ bnv,
    const float* __restrict__ W2, const float* __restrict__ b2,
    const int* __restrict__ batch,
    int layer)
{
    extern __shared__ float sm[];
    float* W1f = sm;                 // D*D (BN-folded)
    float* W2s = sm + D * D;         // D*D
    float* b1f = W2s + D * D;        // D (BN-folded)
    float* b2s = b1f + D;            // D
    float* scl = b2s + D;            // D
    float* zbuf = scl + D;           // 16 warps * D

    const int tid = threadIdx.x;

    for (int j = tid; j < D; j += blockDim.x) {
        const float s = bng[j] * rsqrtf(bnv[j] + BN_EPS);
        scl[j] = s;
        b1f[j] = b1[j] * s + (bnb[j] - bnm[j] * s);
        b2s[j] = b2[j];
    }
    __syncthreads();
    for (int i = tid; i < D * D; i += blockDim.x) {
        W1f[i] = W1[i] * scl[i & (D - 1)];
        W2s[i] = W2[i];
    }
    __syncthreads();

    const int lane = tid & 31;
    const int warp = tid >> 5;
    float* zb = zbuf + warp * D;

    const int gw = blockIdx.x * 16 + warp;
    const int nw = gridDim.x * 16;

    for (int n = gw; n < NN; n += nw) {
        const float* hr = h_in + (size_t)n * D;
        const float* ar = g_aggr + (size_t)n * D;

        // z = h + aggr into this warp's shared row
#pragma unroll
        for (int j = 0; j < 4; j++) {
            const int d = lane + 32 * j;
            zb[d] = hr[d] + ar[d];
        }
        __syncwarp();

        // t = relu(z @ W1f + b1f); lane handles dims lane*4 .. lane*4+3
        float t0 = b1f[lane * 4], t1 = b1f[lane * 4 + 1];
        float t2 = b1f[lane * 4 + 2], t3 = b1f[lane * 4 + 3];
#pragma unroll 8
        for (int k = 0; k < D; k += 4) {
            const float4 z4 = *(const float4*)(zb + k);
#pragma unroll
            for (int kk = 0; kk < 4; kk++) {
                const float zk = (kk == 0) ? z4.x : (kk == 1) ? z4.y : (kk == 2) ? z4.z : z4.w;
                const float4 w = *(const float4*)(W1f + (k + kk) * D + lane * 4);
                t0 += zk * w.x; t1 += zk * w.y; t2 += zk * w.z; t3 += zk * w.w;
            }
        }
        t0 = fmaxf(t0, 0.0f); t1 = fmaxf(t1, 0.0f);
        t2 = fmaxf(t2, 0.0f); t3 = fmaxf(t3, 0.0f);

        __syncwarp();
        zb[lane * 4 + 0] = t0; zb[lane * 4 + 1] = t1;
        zb[lane * 4 + 2] = t2; zb[lane * 4 + 3] = t3;
        __syncwarp();

        // u = t @ W2 + b2; h_out = relu(u)
        float u0 = b2s[lane * 4], u1 = b2s[lane * 4 + 1];
        float u2 = b2s[lane * 4 + 2], u3 = b2s[lane * 4 + 3];
#pragma unroll 8
        for (int k = 0; k < D; k += 4) {
            const float4 z4 = *(const float4*)(zb + k);
#pragma unroll
            for (int kk = 0; kk < 4; kk++) {
                const float zk = (kk == 0) ? z4.x : (kk == 1) ? z4.y : (kk == 2) ? z4.z : z4.w;
                const float4 w = *(const float4*)(W2s + (k + kk) * D + lane * 4);
                u0 += zk * w.x; u1 += zk * w.y; u2 += zk * w.z; u3 += zk * w.w;
            }
        }
        u0 = fmaxf(u0, 0.0f); u1 = fmaxf(u1, 0.0f);
        u2 = fmaxf(u2, 0.0f); u3 = fmaxf(u3, 0.0f);

        float4 ho; ho.x = u0; ho.y = u1; ho.z = u2; ho.w = u3;
        *(float4*)(g_h + (size_t)n * D + lane * 4) = ho;

        const int b = batch[n];
        float* pp = g_pool + (size_t)b * (NL * D) + layer * D + lane * 4;
        atomicAdd(pp + 0, u0);
        atomicAdd(pp + 1, u1);
        atomicAdd(pp + 2, u2);
        atomicAdd(pp + 3, u3);

        __syncwarp();
    }
}

// ---------------------------------------------------------------------------
// Final MLP: out = relu(g @ lin1_W + lin1_b) @ lin2_W + lin2_b, one block/graph
// ---------------------------------------------------------------------------
__global__ void __launch_bounds__(128) final_kernel(
    const float* __restrict__ lin1W, const float* __restrict__ lin1b,
    const float* __restrict__ lin2W, const float* __restrict__ lin2b,
    float* __restrict__ out)
{
    __shared__ float sg[NL * D];
    __shared__ float red[4];
    const int g = blockIdx.x;
    const int tid = threadIdx.x;

    for (int i = tid; i < NL * D; i += 128) sg[i] = g_pool[(size_t)g * NL * D + i];
    __syncthreads();

    float partial = 0.0f;
#pragma unroll
    for (int jj = 0; jj < 3; jj++) {
        const int j = tid + jj * 128;
        float acc = lin1b[j];
        for (int k = 0; k < NL * D; k++)
            acc += sg[k] * lin1W[k * (NL * D) + j];
        partial += fmaxf(acc, 0.0f) * lin2W[j];
    }

    for (int o = 16; o > 0; o >>= 1)
        partial += __shfl_down_sync(0xffffffffu, partial, o);
    if ((tid & 31) == 0) red[tid >> 5] = partial;
    __syncthreads();
    if (tid == 0) out[g] = red[0] + red[1] + red[2] + red[3] + lin2b[0];
}

// ---------------------------------------------------------------------------
extern "C" void kernel_launch(void* const* d_in, const int* in_sizes, int n_in,
                              void* d_out, int out_size)
{
    const float* x    = (const float*)d_in[0];
    const float* ea   = (const float*)d_in[1];
    const float* elW  = (const float*)d_in[2];
    const float* elb  = (const float*)d_in[3];
    const float* W1   = (const float*)d_in[4];
    const float* b1   = (const float*)d_in[5];
    const float* bng  = (const float*)d_in[6];
    const float* bnb  = (const float*)d_in[7];
    const float* bnm  = (const float*)d_in[8];
    const float* bnv  = (const float*)d_in[9];
    const float* W2   = (const float*)d_in[10];
    const float* b2   = (const float*)d_in[11];
    const float* l1W  = (const float*)d_in[12];
    const float* l1b  = (const float*)d_in[13];
    const float* l2W  = (const float*)d_in[14];
    const float* l2b  = (const float*)d_in[15];
    const int* ei     = (const int*)d_in[16];
    const int* batch  = (const int*)d_in[17];
    float* out = (float*)d_out;

    void* aggr_p = nullptr; cudaGetSymbolAddress(&aggr_p, g_aggr);
    void* pool_p = nullptr; cudaGetSymbolAddress(&pool_p, g_pool);
    void* h_p    = nullptr; cudaGetSymbolAddress(&h_p, g_h);

    const size_t NODE_SMEM = (size_t)(2 * D * D + 3 * D + 16 * D) * sizeof(float);
    cudaFuncSetAttribute(node_kernel, cudaFuncAttributeMaxDynamicSharedMemorySize,
                         (int)NODE_SMEM);

    cudaMemsetAsync(pool_p, 0, (size_t)NG * NL * D * sizeof(float), 0);

    const float* h = x;
    for (int l = 0; l < NL; l++) {
        cudaMemsetAsync(aggr_p, 0, (size_t)NN * D * sizeof(float), 0);
        edge_kernel<<<2368, 256>>>(h, ea, elW + (size_t)l * EF * D, elb + (size_t)l * D, ei);
        node_kernel<<<148, 512, NODE_SMEM>>>(h,
            W1 + (size_t)l * D * D, b1 + (size_t)l * D,
            bng + (size_t)l * D, bnb + (size_t)l * D,
            bnm + (size_t)l * D, bnv + (size_t)l * D,
            W2 + (size_t)l * D * D, b2 + (size_t)l * D,
            batch, l);
        h = (const float*)h_p;
    }
    final_kernel<<<NG, 128>>>(l1W, l1b, l2W, l2b, out);
}

// round 5
// speedup vs baseline: 1.4516x; 1.4516x over previous
#include <cuda_runtime.h>

#define NN 50000
#define NE 1600000
#define NG 512
#define NL 3
#define D 128
#define EF 16
#define BN_EPS 1e-5f

// Scratch (device globals: allocation-free rule)
__device__ float g_h[NN * D];          // node features after each layer
__device__ float g_z[NN * D];          // z = h + aggr (written by aggr kernel)
__device__ float g_pool[NG * NL * D];  // per-graph pooled features
__device__ int   g_deg[NN];
__device__ int   g_off[NN + 1];
__device__ int   g_cursor[NN];
__device__ int   g_elist[NE];

// ---------------------------------------------------------------------------
// CSR build: histogram of dst
// ---------------------------------------------------------------------------
__global__ void hist_kernel(const int* __restrict__ ei)
{
    int e = blockIdx.x * blockDim.x + threadIdx.x;
    if (e < NE) atomicAdd(&g_deg[ei[NE + e]], 1);
}

// Single-block exclusive scan over g_deg -> g_off (Hillis-Steele per chunk)
__global__ void scan_kernel()
{
    __shared__ int buf[1024];
    __shared__ int carry;
    const int tid = threadIdx.x;
    if (tid == 0) carry = 0;
    __syncthreads();
    for (int base = 0; base < NN; base += 1024) {
        const int i = base + tid;
        const int v = (i < NN) ? g_deg[i] : 0;
        buf[tid] = v;
        __syncthreads();
        for (int o = 1; o < 1024; o <<= 1) {
            int t = (tid >= o) ? buf[tid - o] : 0;
            __syncthreads();
            buf[tid] += t;
            __syncthreads();
        }
        if (i < NN) g_off[i] = carry + buf[tid] - v;
        __syncthreads();
        if (tid == 1023) carry += buf[1023];
        __syncthreads();
    }
    if (tid == 0) g_off[NN] = carry;
}

__global__ void fill_kernel(const int* __restrict__ ei)
{
    int e = blockIdx.x * blockDim.x + threadIdx.x;
    if (e < NE) {
        int pos = atomicAdd(&g_cursor[ei[NE + e]], 1);
        g_elist[pos] = e;
    }
}

// ---------------------------------------------------------------------------
// Aggregation (gather, no atomics): warp per node.
//   z[n] = h[n] + sum_{e: dst=n} relu(h[src(e)] + edge_attr[e] @ elW + elb)
// Edge-linear weights live in registers (16x4 per lane).
// ---------------------------------------------------------------------------
__global__ void __launch_bounds__(256) aggr_kernel(
    const float* __restrict__ h,
    const float* __restrict__ edge_attr,
    const float* __restrict__ elW,   // [EF, D] this layer
    const float* __restrict__ elb,   // [D]
    const int* __restrict__ ei)
{
    const int lane = threadIdx.x & 31;
    const int warp = threadIdx.x >> 5;
    const int n = blockIdx.x * 8 + warp;
    if (n >= NN) return;

    float wr[EF][4];
    float br[4];
    {
        const float4 bb = ((const float4*)elb)[lane];
        br[0] = bb.x; br[1] = bb.y; br[2] = bb.z; br[3] = bb.w;
#pragma unroll
        for (int f = 0; f < EF; f++) {
            const float4 w = ((const float4*)(elW + f * D))[lane];
            wr[f][0] = w.x; wr[f][1] = w.y; wr[f][2] = w.z; wr[f][3] = w.w;
        }
    }

    const int beg = g_off[n];
    const int end = g_off[n + 1];
    float4 acc = make_float4(0.f, 0.f, 0.f, 0.f);

    int e = 0, src = 0;
    if (beg < end) {
        e = g_elist[beg];
        src = ei[e];
    }
    for (int idx = beg; idx < end; idx++) {
        // issue current edge's data loads
        const float4* eap = (const float4*)(edge_attr + (size_t)e * EF);
        const float4 q0 = __ldg(eap + 0);
        const float4 q1 = __ldg(eap + 1);
        const float4 q2 = __ldg(eap + 2);
        const float4 q3 = __ldg(eap + 3);
        const float4 hv = __ldg((const float4*)(h + (size_t)src * D) + lane);

        // prefetch next edge's index chain
        if (idx + 1 < end) {
            e = g_elist[idx + 1];
            src = ei[e];
        }

        float a[EF] = { q0.x, q0.y, q0.z, q0.w, q1.x, q1.y, q1.z, q1.w,
                        q2.x, q2.y, q2.z, q2.w, q3.x, q3.y, q3.z, q3.w };
        float e0 = br[0], e1 = br[1], e2 = br[2], e3 = br[3];
#pragma unroll
        for (int f = 0; f < EF; f++) {
            e0 += a[f] * wr[f][0];
            e1 += a[f] * wr[f][1];
            e2 += a[f] * wr[f][2];
            e3 += a[f] * wr[f][3];
        }
        acc.x += fmaxf(hv.x + e0, 0.0f);
        acc.y += fmaxf(hv.y + e1, 0.0f);
        acc.z += fmaxf(hv.z + e2, 0.0f);
        acc.w += fmaxf(hv.w + e3, 0.0f);
    }

    const float4 hn = __ldg((const float4*)(h + (size_t)n * D) + lane);
    acc.x += hn.x; acc.y += hn.y; acc.z += hn.z; acc.w += hn.w;
    ((float4*)(g_z + (size_t)n * D))[lane] = acc;
}

// ---------------------------------------------------------------------------
// Node MLP: register-blocked, 8 nodes per warp. BN folded into W1/b1.
//   t = relu(z @ W1f + b1f); hN = relu(t @ W2 + b2)
//   g_h[n] = hN; pool[batch[n]] += hN
// ---------------------------------------------------------------------------
__global__ void __launch_bounds__(512) node_kernel(
    const float* __restrict__ W1, const float* __restrict__ b1,
    const float* __restrict__ bng, const float* __restrict__ bnb,
    const float* __restrict__ bnm, const float* __restrict__ bnv,
    const float* __restrict__ W2, const float* __restrict__ b2,
    const int* __restrict__ batch,
    int layer)
{
    extern __shared__ float sm[];
    float* W1f = sm;                  // D*D (BN-folded)
    float* W2s = sm + D * D;          // D*D
    float* b1f = W2s + D * D;         // D
    float* b2s = b1f + D;             // D
    float* scl = b2s + D;             // D
    float* zbuf = scl + D;            // 16 warps * 8 nodes * D

    const int tid = threadIdx.x;

    for (int j = tid; j < D; j += blockDim.x) {
        const float s = bng[j] * rsqrtf(bnv[j] + BN_EPS);
        scl[j] = s;
        b1f[j] = b1[j] * s + (bnb[j] - bnm[j] * s);
        b2s[j] = b2[j];
    }
    __syncthreads();
    for (int i = tid; i < D * D; i += blockDim.x) {
        W1f[i] = W1[i] * scl[i & (D - 1)];
        W2s[i] = W2[i];
    }
    __syncthreads();

    const int lane = tid & 31;
    const int warp = tid >> 5;
    float* zb = zbuf + warp * 8 * D;

    const int gw = blockIdx.x * 16 + warp;
    const int nw = gridDim.x * 16;

    for (int base = gw * 8; base < NN; base += nw * 8) {
        // NN % 8 == 0: always a full tile of 8 nodes
#pragma unroll
        for (int i = 0; i < 8; i++) {
            const float4 v = __ldg((const float4*)(g_z + (size_t)(base + i) * D) + lane);
            ((float4*)(zb + i * D))[lane] = v;
        }
        __syncwarp();

        float4 acc[8];
        {
            const float4 bb = ((const float4*)b1f)[lane];
#pragma unroll
            for (int i = 0; i < 8; i++) acc[i] = bb;
        }
#pragma unroll 4
        for (int k = 0; k < D; k += 4) {
            const float4 w0 = ((const float4*)(W1f + (k + 0) * D))[lane];
            const float4 w1 = ((const float4*)(W1f + (k + 1) * D))[lane];
            const float4 w2 = ((const float4*)(W1f + (k + 2) * D))[lane];
            const float4 w3 = ((const float4*)(W1f + (k + 3) * D))[lane];
#pragma unroll
            for (int i = 0; i < 8; i++) {
                const float4 zv = *(const float4*)(zb + i * D + k);
                acc[i].x += zv.x * w0.x + zv.y * w1.x + zv.z * w2.x + zv.w * w3.x;
                acc[i].y += zv.x * w0.y + zv.y * w1.y + zv.z * w2.y + zv.w * w3.y;
                acc[i].z += zv.x * w0.z + zv.y * w1.z + zv.z * w2.z + zv.w * w3.z;
                acc[i].w += zv.x * w0.w + zv.y * w1.w + zv.z * w2.w + zv.w * w3.w;
            }
        }
        __syncwarp();
#pragma unroll
        for (int i = 0; i < 8; i++) {
            float4 t;
            t.x = fmaxf(acc[i].x, 0.0f); t.y = fmaxf(acc[i].y, 0.0f);
            t.z = fmaxf(acc[i].z, 0.0f); t.w = fmaxf(acc[i].w, 0.0f);
            ((float4*)(zb + i * D))[lane] = t;
        }
        __syncwarp();

        {
            const float4 bb = ((const float4*)b2s)[lane];
#pragma unroll
            for (int i = 0; i < 8; i++) acc[i] = bb;
        }
#pragma unroll 4
        for (int k = 0; k < D; k += 4) {
            const float4 w0 = ((const float4*)(W2s + (k + 0) * D))[lane];
            const float4 w1 = ((const float4*)(W2s + (k + 1) * D))[lane];
            const float4 w2 = ((const float4*)(W2s + (k + 2) * D))[lane];
            const float4 w3 = ((const float4*)(W2s + (k + 3) * D))[lane];
#pragma unroll
            for (int i = 0; i < 8; i++) {
                const float4 zv = *(const float4*)(zb + i * D + k);
                acc[i].x += zv.x * w0.x + zv.y * w1.x + zv.z * w2.x + zv.w * w3.x;
                acc[i].y += zv.x * w0.y + zv.y * w1.y + zv.z * w2.y + zv.w * w3.y;
                acc[i].z += zv.x * w0.z + zv.y * w1.z + zv.z * w2.z + zv.w * w3.z;
                acc[i].w += zv.x * w0.w + zv.y * w1.w + zv.z * w2.w + zv.w * w3.w;
            }
        }
#pragma unroll
        for (int i = 0; i < 8; i++) {
            const int n = base + i;
            float4 u;
            u.x = fmaxf(acc[i].x, 0.0f); u.y = fmaxf(acc[i].y, 0.0f);
            u.z = fmaxf(acc[i].z, 0.0f); u.w = fmaxf(acc[i].w, 0.0f);
            ((float4*)(g_h + (size_t)n * D))[lane] = u;

            const int b = batch[n];
            float* pp = g_pool + (size_t)b * (NL * D) + layer * D + lane * 4;
            atomicAdd(pp + 0, u.x);
            atomicAdd(pp + 1, u.y);
            atomicAdd(pp + 2, u.z);
            atomicAdd(pp + 3, u.w);
        }
        __syncwarp();
    }
}

// ---------------------------------------------------------------------------
// Final MLP: out = relu(g @ lin1_W + lin1_b) @ lin2_W + lin2_b, one block/graph
// ---------------------------------------------------------------------------
__global__ void __launch_bounds__(128) final_kernel(
    const float* __restrict__ lin1W, const float* __restrict__ lin1b,
    const float* __restrict__ lin2W, const float* __restrict__ lin2b,
    float* __restrict__ out)
{
    __shared__ float sg[NL * D];
    __shared__ float red[4];
    const int g = blockIdx.x;
    const int tid = threadIdx.x;

    for (int i = tid; i < NL * D; i += 128) sg[i] = g_pool[(size_t)g * NL * D + i];
    __syncthreads();

    float partial = 0.0f;
#pragma unroll
    for (int jj = 0; jj < 3; jj++) {
        const int j = tid + jj * 128;
        float acc = lin1b[j];
        for (int k = 0; k < NL * D; k++)
            acc += sg[k] * lin1W[k * (NL * D) + j];
        partial += fmaxf(acc, 0.0f) * lin2W[j];
    }

    for (int o = 16; o > 0; o >>= 1)
        partial += __shfl_down_sync(0xffffffffu, partial, o);
    if ((tid & 31) == 0) red[tid >> 5] = partial;
    __syncthreads();
    if (tid == 0) out[g] = red[0] + red[1] + red[2] + red[3] + lin2b[0];
}

// ---------------------------------------------------------------------------
extern "C" void kernel_launch(void* const* d_in, const int* in_sizes, int n_in,
                              void* d_out, int out_size)
{
    const float* x    = (const float*)d_in[0];
    const float* ea   = (const float*)d_in[1];
    const float* elW  = (const float*)d_in[2];
    const float* elb  = (const float*)d_in[3];
    const float* W1   = (const float*)d_in[4];
    const float* b1   = (const float*)d_in[5];
    const float* bng  = (const float*)d_in[6];
    const float* bnb  = (const float*)d_in[7];
    const float* bnm  = (const float*)d_in[8];
    const float* bnv  = (const float*)d_in[9];
    const float* W2   = (const float*)d_in[10];
    const float* b2   = (const float*)d_in[11];
    const float* l1W  = (const float*)d_in[12];
    const float* l1b  = (const float*)d_in[13];
    const float* l2W  = (const float*)d_in[14];
    const float* l2b  = (const float*)d_in[15];
    const int* ei     = (const int*)d_in[16];
    const int* batch  = (const int*)d_in[17];
    float* out = (float*)d_out;

    void* deg_p = nullptr;  cudaGetSymbolAddress(&deg_p, g_deg);
    void* off_p = nullptr;  cudaGetSymbolAddress(&off_p, g_off);
    void* cur_p = nullptr;  cudaGetSymbolAddress(&cur_p, g_cursor);
    void* pool_p = nullptr; cudaGetSymbolAddress(&pool_p, g_pool);
    void* h_p    = nullptr; cudaGetSymbolAddress(&h_p, g_h);

    const size_t NODE_SMEM =
        (size_t)(2 * D * D + 3 * D + 16 * 8 * D) * sizeof(float);
    cudaFuncSetAttribute(node_kernel, cudaFuncAttributeMaxDynamicSharedMemorySize,
                         (int)NODE_SMEM);

    // CSR build (once per call)
    cudaMemsetAsync(deg_p, 0, NN * sizeof(int), 0);
    hist_kernel<<<(NE + 255) / 256, 256>>>(ei);
    scan_kernel<<<1, 1024>>>();
    cudaMemcpyAsync(cur_p, off_p, NN * sizeof(int), cudaMemcpyDeviceToDevice, 0);
    fill_kernel<<<(NE + 255) / 256, 256>>>(ei);

    cudaMemsetAsync(pool_p, 0, (size_t)NG * NL * D * sizeof(float), 0);

    const float* h = x;
    for (int l = 0; l < NL; l++) {
        aggr_kernel<<<(NN + 7) / 8, 256>>>(h, ea,
            elW + (size_t)l * EF * D, elb + (size_t)l * D, ei);
        node_kernel<<<148, 512, NODE_SMEM>>>(
            W1 + (size_t)l * D * D, b1 + (size_t)l * D,
            bng + (size_t)l * D, bnb + (size_t)l * D,
            bnm + (size_t)l * D, bnv + (size_t)l * D,
            W2 + (size_t)l * D * D, b2 + (size_t)l * D,
            batch, l);
        h = (const float*)h_p;
    }
    final_kernel<<<NG, 128>>>(l1W, l1b, l2W, l2b, out);
}

// round 9
// speedup vs baseline: 2.7318x; 1.8819x over previous
#include <cuda_runtime.h>

#define NN 50000
#define NE 1600000
#define NG 512
#define NL 3
#define D 128
#define EF 16
#define BN_EPS 1e-5f

// Scratch (device globals: allocation-free rule)
__device__ float g_h[NN * D];          // node features after each layer
__device__ float g_z[NN * D];          // z = h + aggr (written by aggr kernel)
__device__ float g_pool[NG * NL * D];  // per-graph pooled features
__device__ int   g_deg[NN];
__device__ int   g_off[NN + 1];
__device__ int   g_cursor[NN];
__device__ int   g_elist[NE];

// ---------------------------------------------------------------------------
// CSR build: histogram of dst
// ---------------------------------------------------------------------------
__global__ void hist_kernel(const int* __restrict__ ei)
{
    int e = blockIdx.x * blockDim.x + threadIdx.x;
    if (e < NE) atomicAdd(&g_deg[ei[NE + e]], 1);
}

// Single-block exclusive scan over g_deg -> g_off
__global__ void scan_kernel()
{
    __shared__ int buf[1024];
    __shared__ int carry;
    const int tid = threadIdx.x;
    if (tid == 0) carry = 0;
    __syncthreads();
    for (int base = 0; base < NN; base += 1024) {
        const int i = base + tid;
        const int v = (i < NN) ? g_deg[i] : 0;
        buf[tid] = v;
        __syncthreads();
        for (int o = 1; o < 1024; o <<= 1) {
            int t = (tid >= o) ? buf[tid - o] : 0;
            __syncthreads();
            buf[tid] += t;
            __syncthreads();
        }
        if (i < NN) g_off[i] = carry + buf[tid] - v;
        __syncthreads();
        if (tid == 1023) carry += buf[1023];
        __syncthreads();
    }
    if (tid == 0) g_off[NN] = carry;
}

__global__ void fill_kernel(const int* __restrict__ ei)
{
    int e = blockIdx.x * blockDim.x + threadIdx.x;
    if (e < NE) {
        int pos = atomicAdd(&g_cursor[ei[NE + e]], 1);
        g_elist[pos] = e;
    }
}

// ---------------------------------------------------------------------------
// Aggregation (gather, no atomics): warp per node, 4-edge software pipeline.
//   z[n] = h[n] + sum_{e: dst=n} relu(h[src(e)] + edge_attr[e] @ elW + elb)
// Edge-linear weights live in registers (16x4 per lane). Attr for 2 edges is
// packed into one 32-lane register and broadcast via shfl.
// ---------------------------------------------------------------------------
__global__ void __launch_bounds__(128) aggr_kernel(
    const float* __restrict__ h,
    const float* __restrict__ edge_attr,
    const float* __restrict__ elW,   // [EF, D] this layer
    const float* __restrict__ elb,   // [D]
    const int* __restrict__ ei)
{
    const int lane = threadIdx.x & 31;
    const int warp = threadIdx.x >> 5;
    const int n = blockIdx.x * 4 + warp;
    if (n >= NN) return;

    float wr[EF][4];
    float br[4];
    {
        const float4 bb = ((const float4*)elb)[lane];
        br[0] = bb.x; br[1] = bb.y; br[2] = bb.z; br[3] = bb.w;
#pragma unroll
        for (int f = 0; f < EF; f++) {
            const float4 w = ((const float4*)(elW + f * D))[lane];
            wr[f][0] = w.x; wr[f][1] = w.y; wr[f][2] = w.z; wr[f][3] = w.w;
        }
    }

    const int beg = g_off[n];
    const int end = g_off[n + 1];
    float4 acc = make_float4(0.f, 0.f, 0.f, 0.f);

    // Current-group state: edge ids + src ids (uniform across warp)
    int ec[4], sc[4];
#pragma unroll
    for (int j = 0; j < 4; j++) {
        ec[j] = (beg + j < end) ? g_elist[beg + j] : -1;
    }
#pragma unroll
    for (int j = 0; j < 4; j++) {
        sc[j] = (ec[j] >= 0) ? ei[ec[j]] : -1;
    }

    for (int idx = beg; idx < end; idx += 4) {
        // Issue this group's data loads (4 independent h rows + 2 attr regs)
        const int ea0 = (lane < 16) ? ec[0] : ec[1];
        const int ea1 = (lane < 16) ? ec[2] : ec[3];
        const float av0 = (ea0 >= 0)
            ? __ldg(edge_attr + (size_t)ea0 * EF + (lane & 15)) : 0.0f;
        const float av1 = (ea1 >= 0)
            ? __ldg(edge_attr + (size_t)ea1 * EF + (lane & 15)) : 0.0f;

        float4 hv[4];
#pragma unroll
        for (int j = 0; j < 4; j++) {
            hv[j] = (sc[j] >= 0)
                ? __ldg((const float4*)(h + (size_t)sc[j] * D) + lane)
                : make_float4(0.f, 0.f, 0.f, 0.f);
        }

        // Prefetch next group's index chain (overlaps with compute below)
        int en[4], sn[4];
#pragma unroll
        for (int j = 0; j < 4; j++) {
            en[j] = (idx + 4 + j < end) ? g_elist[idx + 4 + j] : -1;
        }
#pragma unroll
        for (int j = 0; j < 4; j++) {
            sn[j] = (en[j] >= 0) ? ei[en[j]] : -1;
        }

        // Compute the 4 edges of this group
#pragma unroll
        for (int j = 0; j < 4; j++) {
            float e0 = br[0], e1 = br[1], e2 = br[2], e3 = br[3];
            const float av = (j < 2) ? av0 : av1;
            const int base_lane = (j & 1) << 4;
#pragma unroll
            for (int f = 0; f < EF; f++) {
                const float a = __shfl_sync(0xffffffffu, av, base_lane + f);
                e0 += a * wr[f][0];
                e1 += a * wr[f][1];
                e2 += a * wr[f][2];
                e3 += a * wr[f][3];
            }
            if (idx + j < end) {
                acc.x += fmaxf(hv[j].x + e0, 0.0f);
                acc.y += fmaxf(hv[j].y + e1, 0.0f);
                acc.z += fmaxf(hv[j].z + e2, 0.0f);
                acc.w += fmaxf(hv[j].w + e3, 0.0f);
            }
        }

        // Rotate pipeline
#pragma unroll
        for (int j = 0; j < 4; j++) { ec[j] = en[j]; sc[j] = sn[j]; }
    }

    const float4 hn = __ldg((const float4*)(h + (size_t)n * D) + lane);
    acc.x += hn.x; acc.y += hn.y; acc.z += hn.z; acc.w += hn.w;
    ((float4*)(g_z + (size_t)n * D))[lane] = acc;
}

// ---------------------------------------------------------------------------
// Node MLP: register-blocked, 8 nodes per warp. BN folded into W1/b1.
// ---------------------------------------------------------------------------
__global__ void __launch_bounds__(512) node_kernel(
    const float* __restrict__ W1, const float* __restrict__ b1,
    const float* __restrict__ bng, const float* __restrict__ bnb,
    const float* __restrict__ bnm, const float* __restrict__ bnv,
    const float* __restrict__ W2, const float* __restrict__ b2,
    const int* __restrict__ batch,
    int layer)
{
    extern __shared__ float sm[];
    float* W1f = sm;                  // D*D (BN-folded)
    float* W2s = sm + D * D;          // D*D
    float* b1f = W2s + D * D;         // D
    float* b2s = b1f + D;             // D
    float* scl = b2s + D;             // D
    float* zbuf = scl + D;            // 16 warps * 8 nodes * D

    const int tid = threadIdx.x;

    for (int j = tid; j < D; j += blockDim.x) {
        const float s = bng[j] * rsqrtf(bnv[j] + BN_EPS);
        scl[j] = s;
        b1f[j] = b1[j] * s + (bnb[j] - bnm[j] * s);
        b2s[j] = b2[j];
    }
    __syncthreads();
    for (int i = tid; i < D * D; i += blockDim.x) {
        W1f[i] = W1[i] * scl[i & (D - 1)];
        W2s[i] = W2[i];
    }
    __syncthreads();

    const int lane = tid & 31;
    const int warp = tid >> 5;
    float* zb = zbuf + warp * 8 * D;

    const int gw = blockIdx.x * 16 + warp;
    const int nw = gridDim.x * 16;

    for (int base = gw * 8; base < NN; base += nw * 8) {
#pragma unroll
        for (int i = 0; i < 8; i++) {
            const float4 v = __ldg((const float4*)(g_z + (size_t)(base + i) * D) + lane);
            ((float4*)(zb + i * D))[lane] = v;
        }
        __syncwarp();

        float4 acc[8];
        {
            const float4 bb = ((const float4*)b1f)[lane];
#pragma unroll
            for (int i = 0; i < 8; i++) acc[i] = bb;
        }
#pragma unroll 4
        for (int k = 0; k < D; k += 4) {
            const float4 w0 = ((const float4*)(W1f + (k + 0) * D))[lane];
            const float4 w1 = ((const float4*)(W1f + (k + 1) * D))[lane];
            const float4 w2 = ((const float4*)(W1f + (k + 2) * D))[lane];
            const float4 w3 = ((const float4*)(W1f + (k + 3) * D))[lane];
#pragma unroll
            for (int i = 0; i < 8; i++) {
                const float4 zv = *(const float4*)(zb + i * D + k);
                acc[i].x += zv.x * w0.x + zv.y * w1.x + zv.z * w2.x + zv.w * w3.x;
                acc[i].y += zv.x * w0.y + zv.y * w1.y + zv.z * w2.y + zv.w * w3.y;
                acc[i].z += zv.x * w0.z + zv.y * w1.z + zv.z * w2.z + zv.w * w3.z;
                acc[i].w += zv.x * w0.w + zv.y * w1.w + zv.z * w2.w + zv.w * w3.w;
            }
        }
        __syncwarp();
#pragma unroll
        for (int i = 0; i < 8; i++) {
            float4 t;
            t.x = fmaxf(acc[i].x, 0.0f); t.y = fmaxf(acc[i].y, 0.0f);
            t.z = fmaxf(acc[i].z, 0.0f); t.w = fmaxf(acc[i].w, 0.0f);
            ((float4*)(zb + i * D))[lane] = t;
        }
        __syncwarp();

        {
            const float4 bb = ((const float4*)b2s)[lane];
#pragma unroll
            for (int i = 0; i < 8; i++) acc[i] = bb;
        }
#pragma unroll 4
        for (int k = 0; k < D; k += 4) {
            const float4 w0 = ((const float4*)(W2s + (k + 0) * D))[lane];
            const float4 w1 = ((const float4*)(W2s + (k + 1) * D))[lane];
            const float4 w2 = ((const float4*)(W2s + (k + 2) * D))[lane];
            const float4 w3 = ((const float4*)(W2s + (k + 3) * D))[lane];
#pragma unroll
            for (int i = 0; i < 8; i++) {
                const float4 zv = *(const float4*)(zb + i * D + k);
                acc[i].x += zv.x * w0.x + zv.y * w1.x + zv.z * w2.x + zv.w * w3.x;
                acc[i].y += zv.x * w0.y + zv.y * w1.y + zv.z * w2.y + zv.w * w3.y;
                acc[i].z += zv.x * w0.z + zv.y * w1.z + zv.z * w2.z + zv.w * w3.z;
                acc[i].w += zv.x * w0.w + zv.y * w1.w + zv.z * w2.w + zv.w * w3.w;
            }
        }
#pragma unroll
        for (int i = 0; i < 8; i++) {
            const int n = base + i;
            float4 u;
            u.x = fmaxf(acc[i].x, 0.0f); u.y = fmaxf(acc[i].y, 0.0f);
            u.z = fmaxf(acc[i].z, 0.0f); u.w = fmaxf(acc[i].w, 0.0f);
            ((float4*)(g_h + (size_t)n * D))[lane] = u;

            const int b = batch[n];
            float* pp = g_pool + (size_t)b * (NL * D) + layer * D + lane * 4;
            atomicAdd(pp + 0, u.x);
            atomicAdd(pp + 1, u.y);
            atomicAdd(pp + 2, u.z);
            atomicAdd(pp + 3, u.w);
        }
        __syncwarp();
    }
}

// ---------------------------------------------------------------------------
// Final MLP: out = relu(g @ lin1_W + lin1_b) @ lin2_W + lin2_b, one block/graph
// ---------------------------------------------------------------------------
__global__ void __launch_bounds__(128) final_kernel(
    const float* __restrict__ lin1W, const float* __restrict__ lin1b,
    const float* __restrict__ lin2W, const float* __restrict__ lin2b,
    float* __restrict__ out)
{
    __shared__ float sg[NL * D];
    __shared__ float red[4];
    const int g = blockIdx.x;
    const int tid = threadIdx.x;

    for (int i = tid; i < NL * D; i += 128) sg[i] = g_pool[(size_t)g * NL * D + i];
    __syncthreads();

    float partial = 0.0f;
#pragma unroll
    for (int jj = 0; jj < 3; jj++) {
        const int j = tid + jj * 128;
        float acc = lin1b[j];
        for (int k = 0; k < NL * D; k++)
            acc += sg[k] * lin1W[k * (NL * D) + j];
        partial += fmaxf(acc, 0.0f) * lin2W[j];
    }

    for (int o = 16; o > 0; o >>= 1)
        partial += __shfl_down_sync(0xffffffffu, partial, o);
    if ((tid & 31) == 0) red[tid >> 5] = partial;
    __syncthreads();
    if (tid == 0) out[g] = red[0] + red[1] + red[2] + red[3] + lin2b[0];
}

// ---------------------------------------------------------------------------
extern "C" void kernel_launch(void* const* d_in, const int* in_sizes, int n_in,
                              void* d_out, int out_size)
{
    const float* x    = (const float*)d_in[0];
    const float* ea   = (const float*)d_in[1];
    const float* elW  = (const float*)d_in[2];
    const float* elb  = (const float*)d_in[3];
    const float* W1   = (const float*)d_in[4];
    const float* b1   = (const float*)d_in[5];
    const float* bng  = (const float*)d_in[6];
    const float* bnb  = (const float*)d_in[7];
    const float* bnm  = (const float*)d_in[8];
    const float* bnv  = (const float*)d_in[9];
    const float* W2   = (const float*)d_in[10];
    const float* b2   = (const float*)d_in[11];
    const float* l1W  = (const float*)d_in[12];
    const float* l1b  = (const float*)d_in[13];
    const float* l2W  = (const float*)d_in[14];
    const float* l2b  = (const float*)d_in[15];
    const int* ei     = (const int*)d_in[16];
    const int* batch  = (const int*)d_in[17];
    float* out = (float*)d_out;

    void* deg_p = nullptr;  cudaGetSymbolAddress(&deg_p, g_deg);
    void* off_p = nullptr;  cudaGetSymbolAddress(&off_p, g_off);
    void* cur_p = nullptr;  cudaGetSymbolAddress(&cur_p, g_cursor);
    void* pool_p = nullptr; cudaGetSymbolAddress(&pool_p, g_pool);
    void* h_p    = nullptr; cudaGetSymbolAddress(&h_p, g_h);

    const size_t NODE_SMEM =
        (size_t)(2 * D * D + 3 * D + 16 * 8 * D) * sizeof(float);
    cudaFuncSetAttribute(node_kernel, cudaFuncAttributeMaxDynamicSharedMemorySize,
                         (int)NODE_SMEM);

    // CSR build (once per call)
    cudaMemsetAsync(deg_p, 0, NN * sizeof(int), 0);
    hist_kernel<<<(NE + 255) / 256, 256>>>(ei);
    scan_kernel<<<1, 1024>>>();
    cudaMemcpyAsync(cur_p, off_p, NN * sizeof(int), cudaMemcpyDeviceToDevice, 0);
    fill_kernel<<<(NE + 255) / 256, 256>>>(ei);

    cudaMemsetAsync(pool_p, 0, (size_t)NG * NL * D * sizeof(float), 0);

    const float* h = x;
    for (int l = 0; l < NL; l++) {
        aggr_kernel<<<(NN + 3) / 4, 128>>>(h, ea,
            elW + (size_t)l * EF * D, elb + (size_t)l * D, ei);
        node_kernel<<<148, 512, NODE_SMEM>>>(
            W1 + (size_t)l * D * D, b1 + (size_t)l * D,
            bng + (size_t)l * D, bnb + (size_t)l * D,
            bnm + (size_t)l * D, bnv + (size_t)l * D,
            W2 + (size_t)l * D * D, b2 + (size_t)l * D,
            batch, l);
        h = (const float*)h_p;
    }
    final_kernel<<<NG, 128>>>(l1W, l1b, l2W, l2b, out);
}